// round 5
// baseline (speedup 1.0000x reference)
#include <cuda_runtime.h>
#include <math.h>

// SoftSkeletonLoss reduces analytically:
//  - soft_skeletonize(sigmoid-range input) == 0 everywhere after iter 1
//    (conv3x3x3 of a strictly positive field is >0 -> eroded=opened=1 ->
//     skeleton = clip(x-1,0,1) = 0), so skeleton_loss = 1 - EPS/EPS = 0.
//  - Remaining: connectivity_loss = |comp_p - comp_t| where
//      comp = cnt * max(cnt,1) / (sum_masked(conv3x3x3(field)) + EPS*cnt)
//    pred: field = (pred > 0) binarized (sigmoid(x)>0.5 <=> x>0), mask = field
//    target: field = target raw, mask = target > 0

#define DIMV   192
#define TX     32
#define TY     32
#define CHUNK  24
#define NCHUNK (DIMV / CHUNK)   // 8 z-chunks per sample
#define HTW    34                // halo tile width (TX+2)
#define HTILE  (HTW * HTW)       // 1156

// cnt_p, sum_p, cnt_t, sum_t
__device__ double g_acc[4];

__global__ void init_acc_kernel() {
    if (threadIdx.x < 4) g_acc[threadIdx.x] = 0.0;
}

__global__ __launch_bounds__(1024, 1)
void count_kernel(const float* __restrict__ pred,
                  const float* __restrict__ target) {
    __shared__ float sP[2][HTILE];
    __shared__ float sT[2][HTILE];
    __shared__ float red[32][4];

    const int tx  = threadIdx.x;
    const int ty  = threadIdx.y;
    const int tid = ty * 32 + tx;
    const int tx0 = blockIdx.x * TX;
    const int ty0 = blockIdx.y * TY;
    const int c   = blockIdx.z;
    const int n   = c / NCHUNK;           // sample index (0..1)
    const int z0  = (c % NCHUNK) * CHUNK; // z chunk start

    const size_t base = (size_t)n * (size_t)(DIMV * DIMV * DIMV);

    // Cooperative load of plane zp (with xy halo) into smem buffer `buf`.
    // pred is binarized on load; out-of-range -> 0 (SAME zero padding).
    auto load_plane = [&](int zp, int buf) {
        for (int i = tid; i < HTILE; i += 1024) {
            int ly = i / HTW;
            int lx = i - ly * HTW;
            int gy = ty0 + ly - 1;
            int gx = tx0 + lx - 1;
            float pv = 0.0f, tv = 0.0f;
            if ((unsigned)zp < (unsigned)DIMV &&
                (unsigned)gy < (unsigned)DIMV &&
                (unsigned)gx < (unsigned)DIMV) {
                size_t idx = base + (((size_t)zp * DIMV + gy) * DIMV + gx);
                float p = __ldg(pred + idx);
                pv = (p > 0.0f) ? 1.0f : 0.0f;
                tv = __ldg(target + idx);
            }
            sP[buf][i] = pv;
            sT[buf][i] = tv;
        }
    };

    // 3x3 plane sum around this thread's center (local (ty+1, tx+1))
    auto p9 = [&](const float* s) -> float {
        const float* r0 = s + ty * HTW + tx;
        return r0[0]        + r0[1]        + r0[2]
             + r0[HTW]      + r0[HTW + 1]  + r0[HTW + 2]
             + r0[2 * HTW]  + r0[2 * HTW + 1] + r0[2 * HTW + 2];
    };
    const int ctr = (ty + 1) * HTW + (tx + 1);

    // Prologue: plane z0-1 -> buf0, plane z0 -> buf1
    load_plane(z0 - 1, 0);
    __syncthreads();
    float ppPrev = p9(sP[0]);
    float tpPrev = p9(sT[0]);

    load_plane(z0, 1);
    __syncthreads();
    float ppCur = p9(sP[1]);
    float tpCur = p9(sT[1]);
    float cP = sP[1][ctr];
    float cT = sT[1][ctr];

    float cnt_p = 0.0f, sum_p = 0.0f;
    float cnt_t = 0.0f, sum_t = 0.0f;

    // Main z sweep: one barrier per plane, double-buffered smem.
    for (int z = z0; z < z0 + CHUNK; ++z) {
        const int buf = (z - z0) & 1;      // plane z+1 destination
        load_plane(z + 1, buf);
        __syncthreads();
        float ppNext = p9(sP[buf]);
        float tpNext = p9(sT[buf]);
        float cPn = sP[buf][ctr];
        float cTn = sT[buf][ctr];

        if (cP > 0.0f) { cnt_p += 1.0f; sum_p += ppPrev + ppCur + ppNext; }
        if (cT > 0.0f) { cnt_t += 1.0f; sum_t += tpPrev + tpCur + tpNext; }

        ppPrev = ppCur; ppCur = ppNext; cP = cPn;
        tpPrev = tpCur; tpCur = tpNext; cT = cTn;
    }

    // ---- block reduction ----
    #pragma unroll
    for (int o = 16; o; o >>= 1) {
        cnt_p += __shfl_down_sync(0xffffffffu, cnt_p, o);
        sum_p += __shfl_down_sync(0xffffffffu, sum_p, o);
        cnt_t += __shfl_down_sync(0xffffffffu, cnt_t, o);
        sum_t += __shfl_down_sync(0xffffffffu, sum_t, o);
    }
    const int wid  = tid >> 5;
    const int lane = tid & 31;
    if (lane == 0) {
        red[wid][0] = cnt_p; red[wid][1] = sum_p;
        red[wid][2] = cnt_t; red[wid][3] = sum_t;
    }
    __syncthreads();
    if (wid == 0) {
        float v0 = red[lane][0];
        float v1 = red[lane][1];
        float v2 = red[lane][2];
        float v3 = red[lane][3];
        #pragma unroll
        for (int o = 16; o; o >>= 1) {
            v0 += __shfl_down_sync(0xffffffffu, v0, o);
            v1 += __shfl_down_sync(0xffffffffu, v1, o);
            v2 += __shfl_down_sync(0xffffffffu, v2, o);
            v3 += __shfl_down_sync(0xffffffffu, v3, o);
        }
        if (lane == 0) {
            atomicAdd(&g_acc[0], (double)v0);
            atomicAdd(&g_acc[1], (double)v1);
            atomicAdd(&g_acc[2], (double)v2);
            atomicAdd(&g_acc[3], (double)v3);
        }
    }
}

__global__ void finalize_kernel(float* __restrict__ out, int out_size) {
    const double eps = 1e-8;
    double cp = g_acc[0], sp = g_acc[1];
    double ct = g_acc[2], st = g_acc[3];
    // mean_nb = sum(neighbors + EPS over mask) / max(cnt, 1)
    double mean_p = (sp + eps * cp) / fmax(cp, 1.0);
    double mean_t = (st + eps * ct) / fmax(ct, 1.0);
    double comp_p = cp / mean_p;
    double comp_t = ct / mean_t;
    // skeleton_loss == 0 exactly (see header comment)
    float loss = (float)fabs(comp_p - comp_t);
    for (int i = threadIdx.x; i < out_size; i += blockDim.x) out[i] = loss;
}

extern "C" void kernel_launch(void* const* d_in, const int* in_sizes, int n_in,
                              void* d_out, int out_size) {
    const float* pred   = (const float*)d_in[0];
    const float* target = (const float*)d_in[1];

    init_acc_kernel<<<1, 32>>>();

    dim3 grid(DIMV / TX, DIMV / TY, 2 * NCHUNK);  // 6 x 6 x 16 = 576 blocks
    dim3 blk(TX, TY);                             // 1024 threads
    count_kernel<<<grid, blk>>>(pred, target);

    finalize_kernel<<<1, 32>>>((float*)d_out, out_size);
}

// round 6
// speedup vs baseline: 1.3124x; 1.3124x over previous
#include <cuda_runtime.h>
#include <math.h>

// SoftSkeletonLoss reduces analytically:
//  - soft_skeletonize(sigmoid-range input) == 0 everywhere after iteration 1
//    (conv3x3x3 of a strictly positive field is > 0 -> eroded = opened = 1 ->
//     skeleton = clip(x - 1, 0, 1) = 0), so skeleton_loss = 1 - EPS/EPS = 0.
//  - Remaining: connectivity_loss = |comp_p - comp_t| where
//      comp = cnt / mean_nb,  mean_nb = (sum_masked(conv3x3x3(field)) + EPS*cnt) / max(cnt,1)
//    pred:   field = (pred > 0) binarized (sigmoid(x) > 0.5 <=> x > 0), mask = field
//    target: field = target raw,                                       mask = target > 0
//
// One fused 27-point-stencil reduction pass over both tensors.

#define DIMV   192
#define TILE   32            // x/y tile of output voxels per block
#define CHUNK  48            // z planes per block
#define HW     34            // halo tile extent (TILE + 2)
#define SROW   40            // smem row stride in floats (16B aligned, bank shift 8)
#define SPLANE (HW * SROW)   // 1360 floats per plane buffer

// g_acc: cnt_p, sum_p, cnt_t, sum_t
__device__ double g_acc[4];

__global__ void init_acc_kernel() {
    if (threadIdx.x < 4) g_acc[threadIdx.x] = 0.0;
}

__global__ __launch_bounds__(256, 4)
void count_kernel(const float* __restrict__ pred,
                  const float* __restrict__ target) {
    __shared__ float sm[2][SPLANE];
    __shared__ float red[8][2];

    const int tx  = threadIdx.x;             // 0..7  (each owns 4 x-voxels)
    const int ty  = threadIdx.y;             // 0..31
    const int tid = ty * 8 + tx;
    const int bx0 = blockIdx.x * TILE;
    const int by0 = blockIdx.y * TILE;

    const int  zc     = blockIdx.z;          // 0..15
    const bool isPred = (zc < 8);
    const int  s      = isPred ? zc : (zc - 8);   // 0..7
    const int  n      = s >> 2;                    // sample
    const int  z0     = (s & 3) * CHUNK;           // z chunk start

    const float* __restrict__ src =
        (isPred ? pred : target) + (size_t)n * (size_t)(DIMV * DIMV * DIMV);

    // ---- cooperative halo-plane load (SAME zero padding) ----
    auto load_plane = [&](int zp, int buf) {
        const bool zin = ((unsigned)zp < (unsigned)DIMV);
        const float* plane = src + (size_t)zp * (DIMV * DIMV);
        #pragma unroll
        for (int i = tid; i < HW * HW; i += 256) {
            int ly = i / HW;
            int lc = i - ly * HW;
            int gy = by0 + ly - 1;
            int gx = bx0 + lc - 1;
            float v = 0.0f;
            if (zin && (unsigned)gy < (unsigned)DIMV && (unsigned)gx < (unsigned)DIMV) {
                v = __ldg(plane + gy * DIMV + gx);
                if (isPred) v = (v > 0.0f) ? 1.0f : 0.0f;
            }
            sm[buf][ly * SROW + lc] = v;
        }
    };

    // ---- 3x3 plane sums for this thread's 4 voxels (vectorized) ----
    // Raw col lc <-> gx = bx0 + lc - 1. Output voxel j (of 4) = local x c0+j,
    // needs raw cols c0+j .. c0+j+2, center at raw col c0+j+1.
    const int c0 = 4 * tx;
    auto plane_sums = [&](int buf, float P[4], float C[4]) {
        const float4* r0 = (const float4*)(sm[buf] + (ty    ) * SROW + c0);
        const float4* r1 = (const float4*)(sm[buf] + (ty + 1) * SROW + c0);
        const float4* r2 = (const float4*)(sm[buf] + (ty + 2) * SROW + c0);
        float4 a0 = r0[0], b0 = r0[1];
        float4 a1 = r1[0], b1 = r1[1];
        float4 a2 = r2[0], b2 = r2[1];
        float c[8];
        c[0] = a0.x + a1.x + a2.x;
        c[1] = a0.y + a1.y + a2.y;
        c[2] = a0.z + a1.z + a2.z;
        c[3] = a0.w + a1.w + a2.w;
        c[4] = b0.x + b1.x + b2.x;
        c[5] = b0.y + b1.y + b2.y;
        c[6] = b0.z + b1.z + b2.z;   // c[6],c[7] may include pad garbage — never consumed
        c[7] = 0.0f;
        P[0] = c[0] + c[1] + c[2];
        P[1] = c[1] + c[2] + c[3];
        P[2] = c[2] + c[3] + c[4];
        P[3] = c[3] + c[4] + c[5];
        C[0] = a1.y; C[1] = a1.z; C[2] = a1.w; C[3] = b1.x;
    };

    float pPrev[4], pCur[4], pNext[4], cCur[4], cNext[4], dummy[4];

    // Prologue: plane z0-1 -> buf0, plane z0 -> buf1
    load_plane(z0 - 1, 0);
    __syncthreads();
    plane_sums(0, pPrev, dummy);

    load_plane(z0, 1);
    __syncthreads();
    plane_sums(1, pCur, cCur);

    float cnt = 0.0f, sum = 0.0f;

    // Main sweep: one barrier per plane, double-buffered.
    #pragma unroll 2
    for (int z = z0; z < z0 + CHUNK; ++z) {
        const int buf = (z - z0) & 1;    // destination for plane z+1
        load_plane(z + 1, buf);
        __syncthreads();
        plane_sums(buf, pNext, cNext);

        #pragma unroll
        for (int j = 0; j < 4; ++j) {
            if (cCur[j] > 0.0f) {
                cnt += 1.0f;
                sum += pPrev[j] + pCur[j] + pNext[j];
            }
        }
        #pragma unroll
        for (int j = 0; j < 4; ++j) {
            pPrev[j] = pCur[j]; pCur[j] = pNext[j]; cCur[j] = cNext[j];
        }
    }

    // ---- block reduction (256 threads, 8 warps) ----
    #pragma unroll
    for (int o = 16; o; o >>= 1) {
        cnt += __shfl_down_sync(0xffffffffu, cnt, o);
        sum += __shfl_down_sync(0xffffffffu, sum, o);
    }
    const int wid  = tid >> 5;
    const int lane = tid & 31;
    if (lane == 0) { red[wid][0] = cnt; red[wid][1] = sum; }
    __syncthreads();
    if (tid == 0) {
        float c2 = 0.0f, s2 = 0.0f;
        #pragma unroll
        for (int w = 0; w < 8; ++w) { c2 += red[w][0]; s2 += red[w][1]; }
        const int ai = isPred ? 0 : 2;
        atomicAdd(&g_acc[ai],     (double)c2);
        atomicAdd(&g_acc[ai + 1], (double)s2);
    }
}

__global__ void finalize_kernel(float* __restrict__ out, int out_size) {
    const double eps = 1e-8;
    double cp = g_acc[0], sp = g_acc[1];
    double ct = g_acc[2], st = g_acc[3];
    double mean_p = (sp + eps * cp) / fmax(cp, 1.0);
    double mean_t = (st + eps * ct) / fmax(ct, 1.0);
    double comp_p = cp / mean_p;
    double comp_t = ct / mean_t;
    float loss = (float)fabs(comp_p - comp_t);   // skeleton_loss == 0 exactly
    for (int i = threadIdx.x; i < out_size; i += blockDim.x) out[i] = loss;
}

extern "C" void kernel_launch(void* const* d_in, const int* in_sizes, int n_in,
                              void* d_out, int out_size) {
    const float* pred   = (const float*)d_in[0];
    const float* target = (const float*)d_in[1];

    init_acc_kernel<<<1, 32>>>();

    dim3 grid(DIMV / TILE, DIMV / TILE, 16);   // 6 x 6 x 16 = 576 blocks
    dim3 blk(8, 32);                           // 256 threads
    count_kernel<<<grid, blk>>>(pred, target);

    finalize_kernel<<<1, 32>>>((float*)d_out, out_size);
}

// round 7
// speedup vs baseline: 3.7470x; 2.8551x over previous
#include <cuda_runtime.h>
#include <math.h>

// SoftSkeletonLoss reduces analytically:
//  - soft_skeletonize(sigmoid-range input) == 0 after iteration 1 (conv3x3x3 of a
//    strictly positive field is > 0 -> eroded = opened = 1 -> skeleton = clip(x-1,0,1)=0),
//    so skeleton_loss = 1 - EPS/EPS = 0 exactly.
//  - Remaining: connectivity_loss = |comp_p - comp_t| where
//      comp = cnt / mean_nb,  mean_nb = (sum_masked(conv3x3x3(field)) + EPS*cnt) / max(cnt,1)
//    pred:   field = (pred > 0) binarized (sigmoid(x)>0.5 <=> x>0), mask = field>0 = pred>0
//    target: field = target raw,                                     mask = target>0
//
// Single fused kernel: 27-point box-sum reduction over both tensors, separable
// x-presums in registers, z-sweep with register rings, loads pipelined one plane
// ahead, last-block finalize with replay-safe reset.

#define DIMV   192
#define PLANE  (DIMV * DIMV)      // 36864
#define TILE   32
#define CHUNK  48
#define NZB    (DIMV / CHUNK)     // 4 z-chunks per sample
#define NBLK   (6 * 6 * 16)       // 576 blocks total
#define NTHR   288                // 272 loader items + compute uses 256

// cnt_p, sum_p, cnt_t, sum_t  (zero-initialized at module load; reset each replay)
__device__ double   g_acc[4];
__device__ unsigned g_ticket;

__global__ __launch_bounds__(NTHR, 4)
void fused_skel_kernel(const float* __restrict__ pred,
                       const float* __restrict__ target,
                       float* __restrict__ out, int out_size) {
    __shared__ float sxs[2][34 * 32];   // x-presums, 34 halo rows x 32 output cols
    __shared__ float red[9][2];

    const int tid = threadIdx.x;
    const int bx0 = blockIdx.x * TILE;
    const int by0 = blockIdx.y * TILE;

    const int  zc     = blockIdx.z;            // 0..15
    const bool isPred = (zc < 8);
    const int  s      = isPred ? zc : zc - 8;  // 0..7
    const int  n      = s >> 2;                // sample 0..1
    const int  z0     = (s & 3) * CHUNK;
    const int  zE     = z0 + CHUNK;

    const float* __restrict__ src =
        (isPred ? pred : target) + (size_t)n * ((size_t)DIMV * PLANE);

    // ---- loader identity: item = (ly, jj); xs row ly, float4 chunk jj ----
    const bool lact = (tid < 272);
    const int  ly   = tid >> 3;                // 0..33 (for tid<272)
    const int  jj   = tid & 7;
    const int  gy   = by0 + ly - 1;
    const int  gx0  = bx0 + 4 * jj;
    const bool rowIn = lact && ((unsigned)gy < (unsigned)DIMV);
    const bool hasL  = (gx0 > 0);
    const bool hasR  = (gx0 + 4 < DIMV);

    float4 v = make_float4(0.f, 0.f, 0.f, 0.f);
    float  e0 = 0.f, e1 = 0.f;

    // prefetch raw plane zp into registers (zero-padded SAME boundary)
    auto fetch = [&](int zp) {
        v = make_float4(0.f, 0.f, 0.f, 0.f); e0 = 0.f; e1 = 0.f;
        if (rowIn && (unsigned)zp < (unsigned)DIMV) {
            const float* r = src + (size_t)zp * PLANE + gy * DIMV + gx0;
            v = *(const float4*)r;
            if (hasL) e0 = r[-1];
            if (hasR) e1 = r[4];
        }
    };
    // compute 3-wide x-sums from registers, store one float4 to smem
    auto store_xs = [&](int buf) {
        if (lact) {
            float a0, a1, a2, a3, b0, b1;
            if (isPred) {
                a0 = v.x > 0.f ? 1.f : 0.f; a1 = v.y > 0.f ? 1.f : 0.f;
                a2 = v.z > 0.f ? 1.f : 0.f; a3 = v.w > 0.f ? 1.f : 0.f;
                b0 = e0  > 0.f ? 1.f : 0.f; b1 = e1  > 0.f ? 1.f : 0.f;
            } else { a0 = v.x; a1 = v.y; a2 = v.z; a3 = v.w; b0 = e0; b1 = e1; }
            float4 xs = make_float4(b0 + a0 + a1, a0 + a1 + a2,
                                    a1 + a2 + a3, a2 + a3 + b1);
            *(float4*)&sxs[buf][ly * 32 + 4 * jj] = xs;
        }
    };

    // ---- compute identity: 4 voxels per thread (tid < 256) ----
    const bool cact = (tid < 256);
    const int  tx   = tid & 7;
    const int  ty   = tid >> 3;                // 0..31 when cact
    const float* cbase = src + (by0 + ty) * DIMV + (bx0 + 4 * tx);

    // 3x3 plane sum = y-sum of three xs rows (vector lanes = 4 voxels)
    auto psum = [&](int buf) -> float4 {
        if (!cact) return make_float4(0.f, 0.f, 0.f, 0.f);
        float4 a = *(const float4*)&sxs[buf][(ty    ) * 32 + 4 * tx];
        float4 b = *(const float4*)&sxs[buf][(ty + 1) * 32 + 4 * tx];
        float4 c = *(const float4*)&sxs[buf][(ty + 2) * 32 + 4 * tx];
        return make_float4(a.x + b.x + c.x, a.y + b.y + c.y,
                           a.z + b.z + c.z, a.w + b.w + c.w);
    };
    // raw center values for the mask (mask is value>0 for BOTH arrays)
    auto loadc = [&](int zp) -> float4 {
        if (cact && (unsigned)zp < (unsigned)DIMV)
            return *(const float4*)(cbase + (size_t)zp * PLANE);
        return make_float4(0.f, 0.f, 0.f, 0.f);
    };

    // ---- prologue ----
    float4 cCur = loadc(z0);          // centers(z0), issued early
    fetch(z0 - 1);
    store_xs(0);
    fetch(z0);
    __syncthreads();
    float4 pPrev = psum(0);
    store_xs(1);
    fetch(z0 + 1);
    __syncthreads();
    float4 pCur = psum(1);

    float cnt = 0.f, sum = 0.f;

    // ---- main sweep: regs hold plane z+1; fetch z+2 while computing z ----
    for (int z = z0; z < zE; ++z) {
        const int buf = (z - z0) & 1;           // destination of plane z+1
        store_xs(buf);
        if (z + 2 <= zE) fetch(z + 2);          // prefetch (skipped on last iter)
        float4 cNext = (z + 1 < zE) ? loadc(z + 1)
                                    : make_float4(0.f, 0.f, 0.f, 0.f);
        __syncthreads();
        float4 pNext = psum(buf);

        if (cact) {
            if (cCur.x > 0.f) { cnt += 1.f; sum += pPrev.x + pCur.x + pNext.x; }
            if (cCur.y > 0.f) { cnt += 1.f; sum += pPrev.y + pCur.y + pNext.y; }
            if (cCur.z > 0.f) { cnt += 1.f; sum += pPrev.z + pCur.z + pNext.z; }
            if (cCur.w > 0.f) { cnt += 1.f; sum += pPrev.w + pCur.w + pNext.w; }
        }
        pPrev = pCur; pCur = pNext; cCur = cNext;
    }

    // ---- block reduction (9 warps) ----
    #pragma unroll
    for (int o = 16; o; o >>= 1) {
        cnt += __shfl_down_sync(0xffffffffu, cnt, o);
        sum += __shfl_down_sync(0xffffffffu, sum, o);
    }
    const int wid  = tid >> 5;
    const int lane = tid & 31;
    if (lane == 0) { red[wid][0] = cnt; red[wid][1] = sum; }
    __syncthreads();

    if (tid == 0) {
        float c2 = 0.f, s2 = 0.f;
        #pragma unroll
        for (int w = 0; w < 9; ++w) { c2 += red[w][0]; s2 += red[w][1]; }
        const int ai = isPred ? 0 : 2;
        atomicAdd(&g_acc[ai],     (double)c2);
        atomicAdd(&g_acc[ai + 1], (double)s2);
        __threadfence();
        unsigned t = atomicAdd(&g_ticket, 1u);
        if (t == NBLK - 1) {
            // last block: finalize, write output, reset for next graph replay
            __threadfence();
            double cp = atomicAdd(&g_acc[0], 0.0);
            double sp = atomicAdd(&g_acc[1], 0.0);
            double ct = atomicAdd(&g_acc[2], 0.0);
            double st = atomicAdd(&g_acc[3], 0.0);
            const double eps = 1e-8;
            double mean_p = (sp + eps * cp) / fmax(cp, 1.0);
            double mean_t = (st + eps * ct) / fmax(ct, 1.0);
            double comp_p = cp / mean_p;
            double comp_t = ct / mean_t;
            float loss = (float)fabs(comp_p - comp_t);  // skeleton_loss == 0 exactly
            for (int i = 0; i < out_size; ++i) out[i] = loss;
            g_acc[0] = 0.0; g_acc[1] = 0.0; g_acc[2] = 0.0; g_acc[3] = 0.0;
            __threadfence();
            g_ticket = 0u;
        }
    }
}

extern "C" void kernel_launch(void* const* d_in, const int* in_sizes, int n_in,
                              void* d_out, int out_size) {
    const float* pred   = (const float*)d_in[0];
    const float* target = (const float*)d_in[1];

    dim3 grid(DIMV / TILE, DIMV / TILE, 16);   // 6 x 6 x 16 = 576 blocks
    fused_skel_kernel<<<grid, NTHR>>>(pred, target, (float*)d_out, out_size);
}